// round 11
// baseline (speedup 1.0000x reference)
#include <cuda_runtime.h>
#include <cuda_bf16.h>
#include <cstdint>

#define N_TOTAL 8388608   // 2^23

__device__ float2 g_scratch[N_TOTAL];   // transposed intermediate

__host__ __device__ __forceinline__ constexpr int brev_c(int x, int K) {
    int r = 0;
    for (int b = 0; b < K; b++) r |= ((x >> b) & 1) << (K - 1 - b);
    return r;
}

__device__ __forceinline__ float2 cmul(float2 a, float2 w) {
    return make_float2(a.x * w.x - a.y * w.y, a.x * w.y + a.y * w.x);
}

// Full-prefetch butterfly network (kA: plenty of regs at 512 thr)
template <int S0, int K>
__device__ __forceinline__ void bnet_pf(float2* a, unsigned jj,
                                        const float2* __restrict__ W) {
    float2 tw[(1 << K) - 1];
#pragma unroll
    for (int u = 0; u < K; u++) {
#pragma unroll
        for (int c = 0; c < (1 << u); c++) {
            unsigned idx = (jj << (22 - S0 - u)) + ((unsigned)c << (22 - u));
            tw[(1 << u) - 1 + c] = __ldg(&W[idx]);
        }
    }
#pragma unroll
    for (int u = 0; u < K; u++) {
        const int half = 1 << (K - 1 - u);
#pragma unroll
        for (int t = 0; t < (1 << K) / 2; t++) {
            const int q1 = ((t & ~(half - 1)) << 1) | (t & (half - 1));
            const int q2 = q1 + half;
            const int c = brev_c(q1, K) & ((1 << u) - 1);
            float2 w = tw[(1 << u) - 1 + c];
            float2 p = cmul(a[q2], w);
            float2 tt = a[q1];
            a[q1] = make_float2(tt.x + p.x, tt.y + p.y);
            a[q2] = make_float2(tt.x - p.x, tt.y - p.y);
        }
    }
}

// one butterfly stage u of a K=4 network (registers in-place, bit-rev bookkeeping)
template <int K>
__device__ __forceinline__ void bstage(float2* a, int u, const float2* tw) {
    const int half = 1 << (K - 1 - u);
#pragma unroll
    for (int t = 0; t < (1 << K) / 2; t++) {
        const int q1 = ((t & ~(half - 1)) << 1) | (t & (half - 1));
        const int q2 = q1 + half;
        const int c = brev_c(q1, K) & ((1 << u) - 1);
        float2 w = tw[c];
        float2 p = cmul(a[q2], w);
        float2 tt = a[q1];
        a[q1] = make_float2(tt.x + p.x, tt.y + p.y);
        a[q2] = make_float2(tt.x - p.x, tt.y - p.y);
    }
}

// Streamed-twiddle K=4 network: per-u loads pipelined one stage ahead.
// Keeps <=12 f2 twiddles live (fits 64-reg budget at 1024 thr).
template <int S0>
__device__ __forceinline__ void bnet4_stream(float2* a, unsigned jj,
                                             const float2* __restrict__ W) {
    float2 t0[1], t1[2], t2[4], t3[8];
    t0[0] = __ldg(&W[jj << (22 - S0)]);
#pragma unroll
    for (int c = 0; c < 2; c++)
        t1[c] = __ldg(&W[(jj << (21 - S0)) + ((unsigned)c << 21)]);
    bstage<4>(a, 0, t0);
#pragma unroll
    for (int c = 0; c < 4; c++)
        t2[c] = __ldg(&W[(jj << (20 - S0)) + ((unsigned)c << 20)]);
    bstage<4>(a, 1, t1);
#pragma unroll
    for (int c = 0; c < 8; c++)
        t3[c] = __ldg(&W[(jj << (19 - S0)) + ((unsigned)c << 19)]);
    bstage<4>(a, 2, t2);
    bstage<4>(a, 3, t3);
}

#define SMEM_ELEMS 16384
#define SMEM_BYTES (SMEM_ELEMS * 8)

// ============================================================================
// Kernel A: stages [0,11). R6-exact. Tile = 8 bases x 2048 q, rounds 4+4+3.
// Output transposed: Yt[brev11(q)*4096 + base].
// ============================================================================
__device__ __forceinline__ unsigned phA(unsigned q, unsigned g) {
    unsigned l = (q << 3) | g;
    return l ^ (((l >> 6) & 1u) << 3);
}

__global__ void __launch_bounds__(512, 1)
fft_kA(const float* __restrict__ Xr, const float2* __restrict__ W,
       float2* __restrict__ Yt) {
    extern __shared__ float2 sm2[];

    const unsigned t = threadIdx.x;
    const unsigned g = t & 7u;
    const unsigned rest = t >> 3;
    const unsigned base = blockIdx.x * 8u + g;

#pragma unroll
    for (int pass = 0; pass < 2; pass++) {
        unsigned low7 = rest + 64u * pass;
        float2 a[16];
#pragma unroll
        for (int x = 0; x < 16; x++)
            a[x] = make_float2(
                __ldg(&Xr[base + ((((unsigned)x << 7) | low7) << 12)]), 0.0f);
        bnet_pf<0, 4>(a, 0u, W);
#pragma unroll
        for (int x = 0; x < 16; x++)
            sm2[phA(((unsigned)x << 7) | low7, g)] = a[x];
    }
    __syncthreads();

#pragma unroll
    for (int pass = 0; pass < 2; pass++) {
        unsigned idx2 = rest + 64u * pass;
        unsigned lo3 = idx2 & 7u;
        unsigned H = idx2 >> 3;
        unsigned jj = __brev(H) >> 28;
        float2 a[16];
#pragma unroll
        for (int x = 0; x < 16; x++)
            a[x] = sm2[phA((H << 7) | ((unsigned)x << 3) | lo3, g)];
        bnet_pf<4, 4>(a, jj, W);
#pragma unroll
        for (int x = 0; x < 16; x++)
            sm2[phA((H << 7) | ((unsigned)x << 3) | lo3, g)] = a[x];
    }
    __syncthreads();

#pragma unroll
    for (int pass = 0; pass < 4; pass++) {
        unsigned B = rest + 64u * pass;
        unsigned jj = __brev(B) >> 24;
        float2 a[8];
#pragma unroll
        for (int x = 0; x < 8; x++)
            a[x] = sm2[phA((B << 3) | (unsigned)x, g)];
        bnet_pf<8, 3>(a, jj, W);
#pragma unroll
        for (int x = 0; x < 8; x++) {
            unsigned C = ((unsigned)brev_c(x, 3) << 8) | jj;
            Yt[C * 4096u + base] = a[x];
        }
    }
}

// ============================================================================
// Kernel B: stages [11,23). 1024 threads, radix-16, 16 f2/thread, one pass
// per round. Swizzle ph(l) = l ^ ((l>>4)&15): verified 2-way (minimum) for
// all rounds' access patterns. Streamed twiddles keep regs near 64.
// Output: Out[(brev12(q) << 11) + j], streaming stores.
// ============================================================================
__device__ __forceinline__ unsigned phB(unsigned q, unsigned jg) {
    unsigned l = (q << 2) | jg;
    return l ^ ((l >> 4) & 15u);
}

__global__ void __launch_bounds__(1024, 1)
fft_kB(const float2* __restrict__ In, const float2* __restrict__ W,
       float2* __restrict__ Out) {
    extern __shared__ float2 sm2[];

    const unsigned t = threadIdx.x;
    const unsigned j0 = blockIdx.x * 4u;

    // round 1: bits q[11:8], S0=11. jg1 = t>>8 (warp-uniform), low8 = t&255:
    // warp loads 32 consecutive complex -> coalesced; twiddles warp-uniform.
    {
        const unsigned jg1 = t >> 8;
        const unsigned low8 = t & 255u;
        const unsigned jB1 = j0 + jg1;
        float2 a[16];
#pragma unroll
        for (int x = 0; x < 16; x++)
            a[x] = __ldcs(&In[jB1 * 4096u + (((unsigned)x << 8) | low8)]);
        bnet4_stream<11>(a, jB1, W);
#pragma unroll
        for (int x = 0; x < 16; x++)
            sm2[phB(((unsigned)x << 8) | low8, jg1)] = a[x];
    }
    __syncthreads();

    const unsigned jg = t & 3u;
    const unsigned jB = j0 + jg;

    // round 2: bits q[7:4], S0=15, jj = jB + brev4(q[11:8])<<11
    {
        const unsigned idx2 = t >> 2;          // 0..255
        const unsigned lo4 = idx2 & 15u;
        const unsigned H = idx2 >> 4;
        const unsigned jj = jB + ((__brev(H) >> 28) << 11);
        float2 a[16];
#pragma unroll
        for (int x = 0; x < 16; x++)
            a[x] = sm2[phB((H << 8) | ((unsigned)x << 4) | lo4, jg)];
        bnet4_stream<15>(a, jj, W);
        __syncthreads();   // safe: every thread re-writes exactly its own slots? no -
                           // R2 reads/writes same addresses, barrier only needed after.
#pragma unroll
        for (int x = 0; x < 16; x++)
            sm2[phB((H << 8) | ((unsigned)x << 4) | lo4, jg)] = a[x];
    }
    __syncthreads();

    // round 3: bits q[3:0], S0=19, jj = jB + brev8(q[11:4])<<11
    {
        const unsigned B = t >> 2;             // 0..255
        const unsigned Brev = __brev(B) >> 24;
        const unsigned jj = jB + (Brev << 11);
        float2 a[16];
#pragma unroll
        for (int x = 0; x < 16; x++)
            a[x] = sm2[phB((B << 4) | (unsigned)x, jg)];
        bnet4_stream<19>(a, jj, W);
#pragma unroll
        for (int x = 0; x < 16; x++) {
            unsigned C = ((unsigned)brev_c(x, 4) << 8) | Brev;  // brev12(q)
            __stcs(&Out[(C << 11) + jB], a[x]);
        }
    }
}

// ---------------------------------------------------------------------------
extern "C" void kernel_launch(void* const* d_in, const int* in_sizes, int n_in,
                              void* d_out, int out_size) {
    const float* inp = (const float*)d_in[0];
    const float2* w = (const float2*)d_in[1];
    float2* out = (float2*)d_out;

    float2* scr = nullptr;
    cudaGetSymbolAddress((void**)&scr, g_scratch);

    cudaFuncSetAttribute(fft_kA, cudaFuncAttributeMaxDynamicSharedMemorySize,
                         SMEM_BYTES);
    cudaFuncSetAttribute(fft_kB, cudaFuncAttributeMaxDynamicSharedMemorySize,
                         SMEM_BYTES);

    fft_kA<<<512, 512, SMEM_BYTES>>>(inp, w, scr);    // stages 0..10
    fft_kB<<<512, 1024, SMEM_BYTES>>>(scr, w, out);   // stages 11..22
}

// round 12
// speedup vs baseline: 1.0300x; 1.0300x over previous
#include <cuda_runtime.h>
#include <cuda_bf16.h>
#include <cstdint>

#define N_TOTAL 8388608   // 2^23

// blocked transposed intermediate: S[(base>>3)*16384 + C*8 + (base&7)]
__device__ float2 g_scratch[N_TOTAL];

__host__ __device__ __forceinline__ constexpr int brev_c(int x, int K) {
    int r = 0;
    for (int b = 0; b < K; b++) r |= ((x >> b) & 1) << (K - 1 - b);
    return r;
}

__device__ __forceinline__ float2 cmul(float2 a, float2 w) {
    return make_float2(a.x * w.x - a.y * w.y, a.x * w.y + a.y * w.x);
}

// Full-prefetch in-register DIF butterfly network, K stages at offset S0.
template <int S0, int K>
__device__ __forceinline__ void bnet_pf(float2* a, unsigned jj,
                                        const float2* __restrict__ W) {
    float2 tw[(1 << K) - 1];
#pragma unroll
    for (int u = 0; u < K; u++) {
#pragma unroll
        for (int c = 0; c < (1 << u); c++) {
            unsigned idx = (jj << (22 - S0 - u)) + ((unsigned)c << (22 - u));
            tw[(1 << u) - 1 + c] = __ldg(&W[idx]);
        }
    }
#pragma unroll
    for (int u = 0; u < K; u++) {
        const int half = 1 << (K - 1 - u);
#pragma unroll
        for (int t = 0; t < (1 << K) / 2; t++) {
            const int q1 = ((t & ~(half - 1)) << 1) | (t & (half - 1));
            const int q2 = q1 + half;
            const int c = brev_c(q1, K) & ((1 << u) - 1);
            float2 w = tw[(1 << u) - 1 + c];
            float2 p = cmul(a[q2], w);
            float2 tt = a[q1];
            a[q1] = make_float2(tt.x + p.x, tt.y + p.y);
            a[q2] = make_float2(tt.x - p.x, tt.y - p.y);
        }
    }
}

#define SMEM_ELEMS 16384
#define SMEM_BYTES (SMEM_ELEMS * 8)

// ============================================================================
// Kernel A: stages [0,11). Tile = 8 bases (g) x 2048 q. Rounds 4+4+3.
// R3 lane map B = brev8(v) (v consecutive) -> coalesced 256B stores into the
// blocked scratch layout. Swizzle folds B[7:6] (l[13:12]) into bank bits.
// ============================================================================
__device__ __forceinline__ unsigned phA2(unsigned q, unsigned g) {
    unsigned l = (q << 3) | g;
    return l ^ (((l >> 6) & 1u) << 3) ^ ((l >> 12) & 1u) ^ (((l >> 13) & 1u) << 3);
}

__global__ void __launch_bounds__(512, 1)
fft_kA(const float* __restrict__ Xr, const float2* __restrict__ W,
       float2* __restrict__ Sc) {
    extern __shared__ float2 sm2[];

    const unsigned t = threadIdx.x;
    const unsigned g = t & 7u;
    const unsigned rest = t >> 3;              // 0..63
    const unsigned base = blockIdx.x * 8u + g;

    // round 1: bits q[10:7], S0=0, jj=0 (strided gmem load, imag=0)
#pragma unroll
    for (int pass = 0; pass < 2; pass++) {
        unsigned low7 = rest + 64u * pass;     // q[6:0]
        float2 a[16];
#pragma unroll
        for (int x = 0; x < 16; x++)
            a[x] = make_float2(
                __ldg(&Xr[base + ((((unsigned)x << 7) | low7) << 12)]), 0.0f);
        bnet_pf<0, 4>(a, 0u, W);
#pragma unroll
        for (int x = 0; x < 16; x++)
            sm2[phA2(((unsigned)x << 7) | low7, g)] = a[x];
    }
    __syncthreads();

    // round 2: bits q[6:3], S0=4, jj = brev4(q[10:7])
#pragma unroll
    for (int pass = 0; pass < 2; pass++) {
        unsigned idx2 = rest + 64u * pass;     // 0..127
        unsigned lo3 = idx2 & 7u;              // q[2:0]
        unsigned H = idx2 >> 3;                // q[10:7]
        unsigned jj = __brev(H) >> 28;
        float2 a[16];
#pragma unroll
        for (int x = 0; x < 16; x++)
            a[x] = sm2[phA2((H << 7) | ((unsigned)x << 3) | lo3, g)];
        bnet_pf<4, 4>(a, jj, W);
#pragma unroll
        for (int x = 0; x < 16; x++)
            sm2[phA2((H << 7) | ((unsigned)x << 3) | lo3, g)] = a[x];
    }
    __syncthreads();

    // round 3: bits q[2:0], S0=8, K=3. v = jj consecutive across lanes,
    // B = brev8(v). Stores: Sc[blk*16384 + C*8 + g], C = brev3(x)<<8 | v ->
    // per inst 32 consecutive float2 (256B).
    float2* blkout = Sc + blockIdx.x * 16384u;
#pragma unroll
    for (int pass = 0; pass < 4; pass++) {
        unsigned v = rest + 64u * pass;        // jj, consecutive in lanes
        unsigned B = __brev(v) >> 24;          // q[10:3]
        float2 a[8];
#pragma unroll
        for (int x = 0; x < 8; x++)
            a[x] = sm2[phA2((B << 3) | (unsigned)x, g)];
        bnet_pf<8, 3>(a, v, W);
#pragma unroll
        for (int x = 0; x < 8; x++) {
            unsigned C = ((unsigned)brev_c(x, 3) << 8) | v;  // brev11(q)
            blkout[C * 8u + g] = a[x];
        }
    }
}

// ============================================================================
// Kernel B: stages [11,23). Tile = 4 j x 4096 q, rounds 4+4+4 (R10 structure).
// R1 remapped to read the blocked scratch fully coalesced:
//   lane: jg=(t>>3)&3, qlo=t&7; warp covers one 256B line per inst.
// Output: Out[(brev12(q) << 11) + j], streaming stores.
// ============================================================================
__device__ __forceinline__ unsigned phB(unsigned q, unsigned js) {
    unsigned l = (q << 2) | js;
    return l ^ ((l >> 4) & 3u) ^ (((l >> 6) & 3u) << 2);
}

__global__ void __launch_bounds__(512, 1)
fft_kB(const float2* __restrict__ In, const float2* __restrict__ W,
       float2* __restrict__ Out) {
    extern __shared__ float2 sm2[];

    const unsigned t = threadIdx.x;
    const unsigned j0 = blockIdx.x * 4u;

    // round 1: bits q[11:8], S0=11. Blocked-layout read:
    // In[(q>>3)*16384 + jB*8 + (q&7)], q = x<<8 | (w+16p)<<3 | qlo.
    {
        const unsigned qlo = t & 7u;
        const unsigned jg1 = (t >> 3) & 3u;
        const unsigned w = t >> 5;             // 0..15
        const unsigned jB1 = j0 + jg1;
#pragma unroll
        for (int pass = 0; pass < 2; pass++) {
            unsigned q75 = w + 16u * pass;     // q[7:3]
            float2 a[16];
#pragma unroll
            for (int x = 0; x < 16; x++)
                a[x] = __ldcs(&In[(((unsigned)x << 5) | q75) * 16384u +
                                  jB1 * 8u + qlo]);
            bnet_pf<11, 4>(a, jB1, W);
#pragma unroll
            for (int x = 0; x < 16; x++) {
                unsigned q = ((unsigned)x << 8) | (q75 << 3) | qlo;
                sm2[phB(q, jg1)] = a[x];
            }
        }
    }
    __syncthreads();

    const unsigned jg = t & 3u;
    const unsigned rest = t >> 2;              // 0..127
    const unsigned jB = j0 + jg;

    // round 2: bits q[7:4], S0=15, jj = jB + brev4(q[11:8])<<11
#pragma unroll
    for (int pass = 0; pass < 2; pass++) {
        unsigned idx2 = rest + 128u * pass;    // 0..255
        unsigned lo4 = idx2 & 15u;             // q[3:0]
        unsigned H = idx2 >> 4;                // q[11:8]
        unsigned jj = jB + ((__brev(H) >> 28) << 11);
        float2 a[16];
#pragma unroll
        for (int x = 0; x < 16; x++)
            a[x] = sm2[phB((H << 8) | ((unsigned)x << 4) | lo4, jg)];
        bnet_pf<15, 4>(a, jj, W);
#pragma unroll
        for (int x = 0; x < 16; x++)
            sm2[phB((H << 8) | ((unsigned)x << 4) | lo4, jg)] = a[x];
    }
    __syncthreads();

    // round 3: bits q[3:0], S0=19, jj = jB + brev8(q[11:4])<<11; write out
#pragma unroll
    for (int pass = 0; pass < 2; pass++) {
        unsigned B = rest + 128u * pass;       // q[11:4], 0..255
        unsigned Brev = __brev(B) >> 24;
        unsigned jj = jB + (Brev << 11);
        float2 a[16];
#pragma unroll
        for (int x = 0; x < 16; x++)
            a[x] = sm2[phB((B << 4) | (unsigned)x, jg)];
        bnet_pf<19, 4>(a, jj, W);
#pragma unroll
        for (int x = 0; x < 16; x++) {
            unsigned C = ((unsigned)brev_c(x, 4) << 8) | Brev;  // brev12(q)
            __stcs(&Out[(C << 11) + jB], a[x]);
        }
    }
}

// ---------------------------------------------------------------------------
extern "C" void kernel_launch(void* const* d_in, const int* in_sizes, int n_in,
                              void* d_out, int out_size) {
    const float* inp = (const float*)d_in[0];
    const float2* w = (const float2*)d_in[1];
    float2* out = (float2*)d_out;

    float2* scr = nullptr;
    cudaGetSymbolAddress((void**)&scr, g_scratch);

    cudaFuncSetAttribute(fft_kA, cudaFuncAttributeMaxDynamicSharedMemorySize,
                         SMEM_BYTES);
    cudaFuncSetAttribute(fft_kB, cudaFuncAttributeMaxDynamicSharedMemorySize,
                         SMEM_BYTES);

    fft_kA<<<512, 512, SMEM_BYTES>>>(inp, w, scr);   // stages 0..10
    fft_kB<<<512, 512, SMEM_BYTES>>>(scr, w, out);   // stages 11..22
}